// round 1
// baseline (speedup 1.0000x reference)
#include <cuda_runtime.h>

constexpr int NTR = 4096;
constexpr int NTE = 2048;
constexpr int DIM = 16;
constexpr int BS  = 128;
constexpr int NB  = NTR / BS;   // 32

// ---- scratch (device globals; no runtime allocation) ----
__device__ float g_L [(size_t)NTR * NTR];   // Knn -> L (lower)
__device__ float g_Ks[(size_t)NTR * NTE];   // Kstar (destroyed during V solve)
__device__ float g_V [(size_t)NTR * NTE];   // V = L^{-1} Kstar
__device__ float g_invD[NB * BS * BS];      // per-block inverse of diag L blocks
__device__ float g_panel[(size_t)NTR * BS]; // panel scratch
__device__ float g_xs[NTR * DIM];
__device__ float g_ts[NTE * DIM];
__device__ float g_sqx[NTR];
__device__ float g_sqt[NTE];
__device__ float g_b[NTR];
__device__ float g_y[NTR];                  // Lslashy
__device__ float g_alpha[NTR];
__device__ float g_partM[8 * NTE];
__device__ float g_partV[8 * NTE];
__device__ float g_params[2];               // sigmaf2, sigman2
__device__ float g_scale[DIM];

// ---------------------------------------------------------------- prep
__global__ void k_prep(const float* lsf2, const float* ll2, const float* lsn2) {
    int t = threadIdx.x;
    if (t == 0) { g_params[0] = expf(lsf2[0]); g_params[1] = expf(lsn2[0]); }
    if (t < DIM) g_scale[t] = sqrtf(0.5f * expf(-ll2[t]));
}

__global__ void k_scale(const float* __restrict__ in, float* __restrict__ out,
                        float* __restrict__ sq, int n) {
    int i = blockIdx.x * blockDim.x + threadIdx.x;
    if (i >= n) return;
    float s = 0.f;
#pragma unroll
    for (int d = 0; d < DIM; d++) {
        float v = in[i * DIM + d] * g_scale[d];
        out[i * DIM + d] = v;
        s += v * v;
    }
    sq[i] = s;
}

// ------------------------------------------------------- kernel builders
__global__ void k_build_knn() {
    __shared__ float A[32][DIM];
    __shared__ float B[32][DIM + 1];
    int bi = blockIdx.y * 32, bj = blockIdx.x * 32;
    int t = threadIdx.x;
    for (int idx = t; idx < 32 * DIM; idx += 256) {
        int r = idx / DIM, d = idx % DIM;
        A[r][d] = g_xs[(bi + r) * DIM + d];
        B[r][d] = g_xs[(bj + r) * DIM + d];
    }
    __syncthreads();
    float sf2 = g_params[0], sn2 = g_params[1];
    int tx = t & 31, ty = t >> 5;
    int j = bj + tx;
    float sqj = g_sqx[j];
#pragma unroll
    for (int q = 0; q < 4; q++) {
        int li = ty * 4 + q, i = bi + li;
        float dot = 0.f;
#pragma unroll
        for (int d = 0; d < DIM; d++) dot += A[li][d] * B[tx][d];
        float d2 = fmaxf(g_sqx[i] + sqj - 2.f * dot, 0.f);
        float v = sf2 * expf(-d2);
        if (i == j) v += sn2;
        g_L[(size_t)i * NTR + j] = v;
    }
}

__global__ void k_build_ks() {
    __shared__ float A[32][DIM];
    __shared__ float B[32][DIM + 1];
    int bi = blockIdx.y * 32, bj = blockIdx.x * 32;
    int t = threadIdx.x;
    for (int idx = t; idx < 32 * DIM; idx += 256) {
        int r = idx / DIM, d = idx % DIM;
        A[r][d] = g_xs[(bi + r) * DIM + d];
        B[r][d] = g_ts[(bj + r) * DIM + d];
    }
    __syncthreads();
    float sf2 = g_params[0];
    int tx = t & 31, ty = t >> 5;
    int j = bj + tx;
    float sqj = g_sqt[j];
#pragma unroll
    for (int q = 0; q < 4; q++) {
        int li = ty * 4 + q, i = bi + li;
        float dot = 0.f;
#pragma unroll
        for (int d = 0; d < DIM; d++) dot += A[li][d] * B[tx][d];
        float d2 = fmaxf(g_sqx[i] + sqj - 2.f * dot, 0.f);
        g_Ks[(size_t)i * NTE + j] = sf2 * expf(-d2);
    }
}

// --------------------------------------- fused potrf(128) + triangular inverse
__global__ void k_potrf_invert(int kb) {
    extern __shared__ float sh[];
    float (*S )[BS + 1] = (float (*)[BS + 1])sh;
    float (*Mi)[BS + 1] = (float (*)[BS + 1])(sh + BS * (BS + 1));
    int t = threadIdx.x;
    float* src = g_L + (size_t)(kb * BS) * NTR + kb * BS;
    for (int idx = t; idx < BS * BS; idx += 1024) {
        int r = idx >> 7, c = idx & (BS - 1);
        S[r][c]  = src[(size_t)r * NTR + c];
        Mi[r][c] = (r == c) ? 1.f : 0.f;
    }
    __syncthreads();
    int lane = t & 31, w = t >> 5;
    for (int j = 0; j < BS; j++) {
        if (t == 0) S[j][j] = sqrtf(S[j][j]);
        __syncthreads();
        float rd = 1.f / S[j][j];
        for (int i = j + 1 + t; i < BS; i += 1024) S[i][j] *= rd;
        for (int c = t; c <= j; c += 1024) Mi[j][c] *= rd;
        __syncthreads();
        for (int i = j + 1 + w; i < BS; i += 32) {
            float lij = S[i][j];
            for (int k = j + 1 + lane; k < BS; k += 32) S[i][k] -= lij * S[k][j];
            for (int c = lane; c <= j; c += 32)        Mi[i][c] -= lij * Mi[j][c];
        }
        __syncthreads();
    }
    for (int idx = t; idx < BS * BS; idx += 1024) {
        int r = idx >> 7, c = idx & (BS - 1);
        if (c <= r) src[(size_t)r * NTR + c] = S[r][c];
        g_invD[kb * BS * BS + idx] = (c <= r) ? Mi[r][c] : 0.f;
    }
}

// ------------------------------------------------ K=128 SGEMM (NN/NT, -=/=, syrk)
template <int TB, int SUB, int SYRK>
__global__ void __launch_bounds__(256, 2) k_gemm128(
    const float* __restrict__ A, int lda,
    const float* __restrict__ B, int ldb,
    float* __restrict__ C, int ldc)
{
    if (SYRK && (blockIdx.y < blockIdx.x)) return;
    const int row0 = blockIdx.y * 128;
    const int col0 = blockIdx.x * 128;
    __shared__ __align__(16) float As[8][132];
    __shared__ __align__(16) float Bs[8][132];
    const int t = threadIdx.x;
    const int tx = t & 15, ty = t >> 4;
    float acc[8][8];
#pragma unroll
    for (int i = 0; i < 8; i++)
#pragma unroll
        for (int j = 0; j < 8; j++) acc[i][j] = 0.f;

    const int ra = t >> 1, qa = t & 1;
    for (int k0 = 0; k0 < 128; k0 += 8) {
        float4 va = *(const float4*)(A + (size_t)(row0 + ra) * lda + k0 + qa * 4);
        As[qa * 4 + 0][ra] = va.x; As[qa * 4 + 1][ra] = va.y;
        As[qa * 4 + 2][ra] = va.z; As[qa * 4 + 3][ra] = va.w;
        if (TB) {
            float4 vb = *(const float4*)(B + (size_t)(col0 + ra) * ldb + k0 + qa * 4);
            Bs[qa * 4 + 0][ra] = vb.x; Bs[qa * 4 + 1][ra] = vb.y;
            Bs[qa * 4 + 2][ra] = vb.z; Bs[qa * 4 + 3][ra] = vb.w;
        } else {
            int kk = t >> 5, q = t & 31;
            float4 vb = *(const float4*)(B + (size_t)(k0 + kk) * ldb + col0 + q * 4);
            *(float4*)&Bs[kk][q * 4] = vb;
        }
        __syncthreads();
#pragma unroll
        for (int k = 0; k < 8; k++) {
            float a[8], b[8];
            *(float4*)&a[0] = *(const float4*)&As[k][ty * 8];
            *(float4*)&a[4] = *(const float4*)&As[k][ty * 8 + 4];
            *(float4*)&b[0] = *(const float4*)&Bs[k][tx * 8];
            *(float4*)&b[4] = *(const float4*)&Bs[k][tx * 8 + 4];
#pragma unroll
            for (int i = 0; i < 8; i++)
#pragma unroll
                for (int j = 0; j < 8; j++) acc[i][j] += a[i] * b[j];
        }
        __syncthreads();
    }
#pragma unroll
    for (int i = 0; i < 8; i++) {
        float* p = C + (size_t)(row0 + ty * 8 + i) * ldc + col0 + tx * 8;
        if (SUB) {
            float4 c0 = *(float4*)p, c1 = *(float4*)(p + 4);
            c0.x -= acc[i][0]; c0.y -= acc[i][1]; c0.z -= acc[i][2]; c0.w -= acc[i][3];
            c1.x -= acc[i][4]; c1.y -= acc[i][5]; c1.z -= acc[i][6]; c1.w -= acc[i][7];
            *(float4*)p = c0; *(float4*)(p + 4) = c1;
        } else {
            float4 c0 = make_float4(acc[i][0], acc[i][1], acc[i][2], acc[i][3]);
            float4 c1 = make_float4(acc[i][4], acc[i][5], acc[i][6], acc[i][7]);
            *(float4*)p = c0; *(float4*)(p + 4) = c1;
        }
    }
}

__global__ void k_copy_panel(float* __restrict__ dst, const float* __restrict__ src, int rows) {
    int idx = blockIdx.x * 256 + threadIdx.x;
    if (idx >= rows * 32) return;
    int r = idx >> 5, q = idx & 31;
    *(float4*)(dst + (size_t)r * NTR + q * 4) = *(const float4*)(src + (size_t)r * BS + q * 4);
}

// ------------------------------------------------------------- trsv (blocked)
__global__ void k_trsv_diag_fwd(int kb) {
    __shared__ float sb[BS];
    int t = threadIdx.x;
    sb[t] = g_b[kb * BS + t];
    __syncthreads();
    const float* Mi = g_invD + kb * BS * BS + t * BS;
    float s = 0.f;
#pragma unroll 4
    for (int k = 0; k < BS; k++) s += Mi[k] * sb[k];
    g_y[kb * BS + t] = s;
}

__global__ void k_trsv_upd_fwd(int kb) {
    __shared__ float sy[BS];
    int t = threadIdx.x;
    if (t < BS) sy[t] = g_y[kb * BS + t];
    __syncthreads();
    int i = (kb + 1) * BS + blockIdx.x * 256 + t;
    if (i >= NTR) return;
    const float* row = g_L + (size_t)i * NTR + kb * BS;
    float s = 0.f;
#pragma unroll
    for (int q = 0; q < 32; q++) {
        float4 v = *(const float4*)(row + q * 4);
        s += v.x * sy[q * 4] + v.y * sy[q * 4 + 1] + v.z * sy[q * 4 + 2] + v.w * sy[q * 4 + 3];
    }
    g_b[i] -= s;
}

__global__ void k_trsv_diag_bwd(int kb) {
    __shared__ float sb[BS];
    int t = threadIdx.x;
    sb[t] = g_b[kb * BS + t];
    __syncthreads();
    const float* Mi = g_invD + kb * BS * BS;
    float s = 0.f;
#pragma unroll 4
    for (int j = 0; j < BS; j++) s += Mi[j * BS + t] * sb[j];
    g_alpha[kb * BS + t] = s;
}

__global__ void k_trsv_upd_bwd(int kb) {
    __shared__ float sx[BS];
    int t = threadIdx.x;
    if (t < BS) sx[t] = g_alpha[kb * BS + t];
    __syncthreads();
    int i = blockIdx.x * 256 + t;
    if (i >= kb * BS) return;
    float s = 0.f;
#pragma unroll 4
    for (int j = 0; j < BS; j++) s += g_L[(size_t)(kb * BS + j) * NTR + i] * sx[j];
    g_b[i] -= s;
}

__global__ void k_veccopy(float* dst, const float* src, int n) {
    int i = blockIdx.x * 256 + threadIdx.x;
    if (i < n) dst[i] = src[i];
}

// ----------------------------------------------------------- reductions
__global__ void k_part_mean() {
    __shared__ float sa[512];
    int t = threadIdx.x;                 // 128
    int n0 = blockIdx.y * 512;
    for (int q = t; q < 512; q += 128) sa[q] = g_alpha[n0 + q];
    __syncthreads();
    int m = blockIdx.x * 128 + t;
    float s = 0.f;
    for (int q = 0; q < 512; q++) s += g_Ks[(size_t)(n0 + q) * NTE + m] * sa[q];
    g_partM[blockIdx.y * NTE + m] = s;
}

__global__ void k_part_var() {
    int t = threadIdx.x;
    int n0 = blockIdx.y * 512;
    int m = blockIdx.x * 128 + t;
    float s = 0.f;
    for (int q = 0; q < 512; q++) { float v = g_V[(size_t)(n0 + q) * NTE + m]; s += v * v; }
    g_partV[blockIdx.y * NTE + m] = s;
}

__global__ void k_finalize(float* out) {
    int m = blockIdx.x * 256 + threadIdx.x;
    if (m >= NTE) return;
    float sm = 0.f, sv = 0.f;
#pragma unroll
    for (int p = 0; p < 8; p++) { sm += g_partM[p * NTE + m]; sv += g_partV[p * NTE + m]; }
    out[m] = sm;
    out[NTE + m] = g_params[0] + g_params[1] - sv;
}

// ----------------------------------------------------------------- launch
extern "C" void kernel_launch(void* const* d_in, const int* in_sizes, int n_in,
                              void* d_out, int out_size)
{
    const float* train_x = (const float*)d_in[0];
    const float* train_y = (const float*)d_in[1];
    const float* test_x  = (const float*)d_in[2];
    const float* lsf2    = (const float*)d_in[3];
    const float* ll2     = (const float*)d_in[4];
    const float* lsn2    = (const float*)d_in[5];
    float* out = (float*)d_out;

    float *pL, *pKs, *pV, *pInvD, *pPanel, *pXs, *pTs, *pSqx, *pSqt, *pB, *pY;
    cudaGetSymbolAddress((void**)&pL,    g_L);
    cudaGetSymbolAddress((void**)&pKs,   g_Ks);
    cudaGetSymbolAddress((void**)&pV,    g_V);
    cudaGetSymbolAddress((void**)&pInvD, g_invD);
    cudaGetSymbolAddress((void**)&pPanel,g_panel);
    cudaGetSymbolAddress((void**)&pXs,   g_xs);
    cudaGetSymbolAddress((void**)&pTs,   g_ts);
    cudaGetSymbolAddress((void**)&pSqx,  g_sqx);
    cudaGetSymbolAddress((void**)&pSqt,  g_sqt);
    cudaGetSymbolAddress((void**)&pB,    g_b);
    cudaGetSymbolAddress((void**)&pY,    g_y);

    const size_t smem_pi = 2 * BS * (BS + 1) * sizeof(float);  // ~129 KB
    cudaFuncSetAttribute(k_potrf_invert, cudaFuncAttributeMaxDynamicSharedMemorySize,
                         (int)smem_pi);

    k_prep<<<1, 32>>>(lsf2, ll2, lsn2);
    k_scale<<<(NTR + 255) / 256, 256>>>(train_x, pXs, pSqx, NTR);
    k_scale<<<(NTE + 255) / 256, 256>>>(test_x,  pTs, pSqt, NTE);
    k_build_knn<<<dim3(NTR / 32, NTR / 32), 256>>>();
    k_build_ks <<<dim3(NTE / 32, NTR / 32), 256>>>();

    // ---- blocked Cholesky (right-looking), with diag-block inverses ----
    for (int kb = 0; kb < NB; kb++) {
        k_potrf_invert<<<1, 1024, smem_pi>>>(kb);
        int R = NTR - (kb + 1) * BS;
        if (R > 0) {
            const float* A21 = pL + (size_t)(kb + 1) * BS * NTR + kb * BS;
            // panel: L21 = A21 * invL11^T  (NT)
            k_gemm128<1, 0, 0><<<dim3(1, R / BS), 256>>>(
                A21, NTR, pInvD + kb * BS * BS, BS, pPanel, BS);
            k_copy_panel<<<(R * 32 + 255) / 256, 256>>>(
                pL + (size_t)(kb + 1) * BS * NTR + kb * BS, pPanel, R);
            // syrk: A22 -= L21 * L21^T (lower tiles only)
            float* C22 = pL + (size_t)(kb + 1) * BS * NTR + (kb + 1) * BS;
            k_gemm128<1, 1, 1><<<dim3(R / BS, R / BS), 256>>>(
                pPanel, BS, pPanel, BS, C22, NTR);
        }
    }

    // ---- forward trsv: y = L^{-1} train_outputs ----
    k_veccopy<<<(NTR + 255) / 256, 256>>>(pB, train_y, NTR);
    for (int kb = 0; kb < NB; kb++) {
        k_trsv_diag_fwd<<<1, BS>>>(kb);
        int R = NTR - (kb + 1) * BS;
        if (R > 0) k_trsv_upd_fwd<<<(R + 255) / 256, 256>>>(kb);
    }
    // ---- backward trsv: alpha = L^{-T} y ----
    k_veccopy<<<(NTR + 255) / 256, 256>>>(pB, pY, NTR);
    for (int kb = NB - 1; kb >= 0; kb--) {
        k_trsv_diag_bwd<<<1, BS>>>(kb);
        if (kb > 0) k_trsv_upd_bwd<<<(kb * BS + 255) / 256, 256>>>(kb);
    }

    // ---- pred_mean partials (uses intact Kstar, before V solve) ----
    k_part_mean<<<dim3(NTE / 128, 8), 128>>>();

    // ---- V = L^{-1} Kstar (blocked trsm via invDiag; destroys Ks) ----
    for (int kb = 0; kb < NB; kb++) {
        k_gemm128<0, 0, 0><<<dim3(NTE / 128, 1), 256>>>(
            pInvD + kb * BS * BS, BS,
            pKs + (size_t)kb * BS * NTE, NTE,
            pV  + (size_t)kb * BS * NTE, NTE);
        int R = NTR - (kb + 1) * BS;
        if (R > 0) {
            k_gemm128<0, 1, 0><<<dim3(NTE / 128, R / BS), 256>>>(
                pL + (size_t)(kb + 1) * BS * NTR + kb * BS, NTR,
                pV + (size_t)kb * BS * NTE, NTE,
                pKs + (size_t)(kb + 1) * BS * NTE, NTE);
        }
    }

    k_part_var<<<dim3(NTE / 128, 8), 128>>>();
    k_finalize<<<(NTE + 255) / 256, 256>>>(out);
}

// round 2
// speedup vs baseline: 1.1973x; 1.1973x over previous
#include <cuda_runtime.h>
#include <cstdint>

constexpr int NTR = 4096;
constexpr int NTE = 2048;
constexpr int DIM = 16;
constexpr int BS  = 128;
constexpr int NB  = NTR / BS;   // 32

// ---- scratch (device globals; no runtime allocation) ----
__device__ float g_L [(size_t)NTR * NTR];   // Knn -> L (lower)
__device__ float g_Ks[(size_t)NTR * NTE];   // Kstar (destroyed during V solve)
__device__ float g_V [(size_t)NTR * NTE];   // V = L^{-1} Kstar
__device__ float g_invD[NB * BS * BS];      // per-block inverse of diag L blocks
__device__ float g_panel[(size_t)NTR * BS]; // panel scratch
__device__ float g_xs[NTR * DIM];
__device__ float g_ts[NTE * DIM];
__device__ float g_sqx[NTR];
__device__ float g_sqt[NTE];
__device__ float g_b[NTR];
__device__ float g_y[NTR];                  // Lslashy
__device__ float g_alpha[NTR];
__device__ float g_partM[8 * NTE];
__device__ float g_partV[8 * NTE];
__device__ float g_params[2];               // sigmaf2, sigman2
__device__ float g_scale[DIM];

// ---------------------------------------------------------------- prep
__global__ void k_prep(const float* lsf2, const float* ll2, const float* lsn2) {
    int t = threadIdx.x;
    if (t == 0) { g_params[0] = expf(lsf2[0]); g_params[1] = expf(lsn2[0]); }
    if (t < DIM) g_scale[t] = sqrtf(0.5f * expf(-ll2[t]));
}

__global__ void k_scale(const float* __restrict__ in, float* __restrict__ out,
                        float* __restrict__ sq, int n) {
    int i = blockIdx.x * blockDim.x + threadIdx.x;
    if (i >= n) return;
    float s = 0.f;
#pragma unroll
    for (int d = 0; d < DIM; d++) {
        float v = in[i * DIM + d] * g_scale[d];
        out[i * DIM + d] = v;
        s += v * v;
    }
    sq[i] = s;
}

// ------------------------------------------------------- kernel builders
__global__ void k_build_knn() {
    __shared__ float A[32][DIM];
    __shared__ float B[32][DIM + 1];
    int bi = blockIdx.y * 32, bj = blockIdx.x * 32;
    int t = threadIdx.x;
    for (int idx = t; idx < 32 * DIM; idx += 256) {
        int r = idx / DIM, d = idx % DIM;
        A[r][d] = g_xs[(bi + r) * DIM + d];
        B[r][d] = g_xs[(bj + r) * DIM + d];
    }
    __syncthreads();
    float sf2 = g_params[0], sn2 = g_params[1];
    int tx = t & 31, ty = t >> 5;
    int j = bj + tx;
    float sqj = g_sqx[j];
#pragma unroll
    for (int q = 0; q < 4; q++) {
        int li = ty * 4 + q, i = bi + li;
        float dot = 0.f;
#pragma unroll
        for (int d = 0; d < DIM; d++) dot += A[li][d] * B[tx][d];
        float d2 = fmaxf(g_sqx[i] + sqj - 2.f * dot, 0.f);
        float v = sf2 * expf(-d2);
        if (i == j) v += sn2;
        g_L[(size_t)i * NTR + j] = v;
    }
}

__global__ void k_build_ks() {
    __shared__ float A[32][DIM];
    __shared__ float B[32][DIM + 1];
    int bi = blockIdx.y * 32, bj = blockIdx.x * 32;
    int t = threadIdx.x;
    for (int idx = t; idx < 32 * DIM; idx += 256) {
        int r = idx / DIM, d = idx % DIM;
        A[r][d] = g_xs[(bi + r) * DIM + d];
        B[r][d] = g_ts[(bj + r) * DIM + d];
    }
    __syncthreads();
    float sf2 = g_params[0];
    int tx = t & 31, ty = t >> 5;
    int j = bj + tx;
    float sqj = g_sqt[j];
#pragma unroll
    for (int q = 0; q < 4; q++) {
        int li = ty * 4 + q, i = bi + li;
        float dot = 0.f;
#pragma unroll
        for (int d = 0; d < DIM; d++) dot += A[li][d] * B[tx][d];
        float d2 = fmaxf(g_sqx[i] + sqj - 2.f * dot, 0.f);
        g_Ks[(size_t)i * NTE + j] = sf2 * expf(-d2);
    }
}

// --------------------------------------- fused potrf(128) + triangular inverse
__global__ void k_potrf_invert(int kb) {
    extern __shared__ float sh[];
    float (*S )[BS + 1] = (float (*)[BS + 1])sh;
    float (*Mi)[BS + 1] = (float (*)[BS + 1])(sh + BS * (BS + 1));
    int t = threadIdx.x;
    float* src = g_L + (size_t)(kb * BS) * NTR + kb * BS;
    for (int idx = t; idx < BS * BS; idx += 1024) {
        int r = idx >> 7, c = idx & (BS - 1);
        S[r][c]  = src[(size_t)r * NTR + c];
        Mi[r][c] = (r == c) ? 1.f : 0.f;
    }
    __syncthreads();
    int lane = t & 31, w = t >> 5;
    for (int j = 0; j < BS; j++) {
        if (t == 0) S[j][j] = sqrtf(S[j][j]);
        __syncthreads();
        float rd = 1.f / S[j][j];
        for (int i = j + 1 + t; i < BS; i += 1024) S[i][j] *= rd;
        for (int c = t; c <= j; c += 1024) Mi[j][c] *= rd;
        __syncthreads();
        for (int i = j + 1 + w; i < BS; i += 32) {
            float lij = S[i][j];
            for (int k = j + 1 + lane; k < BS; k += 32) S[i][k] -= lij * S[k][j];
            for (int c = lane; c <= j; c += 32)        Mi[i][c] -= lij * Mi[j][c];
        }
        __syncthreads();
    }
    for (int idx = t; idx < BS * BS; idx += 1024) {
        int r = idx >> 7, c = idx & (BS - 1);
        if (c <= r) src[(size_t)r * NTR + c] = S[r][c];
        g_invD[kb * BS * BS + idx] = (c <= r) ? Mi[r][c] : 0.f;
    }
}

// -------------------------------------------------- tf32 helpers
__device__ __forceinline__ float tf32r(float x) {
    uint32_t u;
    asm("cvt.rna.tf32.f32 %0, %1;" : "=r"(u) : "f"(x));
    return __uint_as_float(u);
}

__device__ __forceinline__ void mma_tf32(float* d, const uint32_t* a, const uint32_t* b) {
    asm volatile(
        "mma.sync.aligned.m16n8k8.row.col.f32.tf32.tf32.f32 "
        "{%0,%1,%2,%3},{%4,%5,%6,%7},{%8,%9},{%0,%1,%2,%3};"
        : "+f"(d[0]), "+f"(d[1]), "+f"(d[2]), "+f"(d[3])
        : "r"(a[0]), "r"(a[1]), "r"(a[2]), "r"(a[3]), "r"(b[0]), "r"(b[1]));
}

// -------------------- K=128 tensor-core GEMM (tf32), NN/NT, =/-=, syrk filter
// C[128x128 tile] = (or -=) A(row0.., lda) * op(B);  TB=1: B row-major [col][k]
template <int TB, int SUB, int SYRK>
__global__ void __launch_bounds__(256, 2) k_gemm128(
    const float* __restrict__ A, int lda,
    const float* __restrict__ B, int ldb,
    float* __restrict__ C, int ldc)
{
    if (SYRK && (blockIdx.y < blockIdx.x)) return;
    const int row0 = blockIdx.y * 128;
    const int col0 = blockIdx.x * 128;
    __shared__ float As[16][136];   // [k][m], bank-conflict-free frag loads
    __shared__ float Bs[16][136];   // [k][n]
    const int t = threadIdx.x;
    const int lane = t & 31, wid = t >> 5;
    const int wm = wid & 3, wn = wid >> 2;       // 4 x 2 warp grid
    const int g = lane >> 2, tig = lane & 3;

    float acc[2][8][4];
#pragma unroll
    for (int i = 0; i < 2; i++)
#pragma unroll
        for (int j = 0; j < 8; j++)
#pragma unroll
            for (int q = 0; q < 4; q++) acc[i][j][q] = 0.f;

    const int ra = t & 127, fa = t >> 7;   // staging indices (A / NT-B)

    for (int k0 = 0; k0 < 128; k0 += 16) {
        // ---- stage A tile 128x16 into As[k][m] (tf32-rounded) ----
        {
            const float* ap = A + (size_t)(row0 + ra) * lda + k0 + fa * 4;
            float4 v0 = *(const float4*)ap;
            float4 v1 = *(const float4*)(ap + 8);
            As[fa * 4 + 0][ra] = tf32r(v0.x); As[fa * 4 + 1][ra] = tf32r(v0.y);
            As[fa * 4 + 2][ra] = tf32r(v0.z); As[fa * 4 + 3][ra] = tf32r(v0.w);
            As[8 + fa * 4 + 0][ra] = tf32r(v1.x); As[8 + fa * 4 + 1][ra] = tf32r(v1.y);
            As[8 + fa * 4 + 2][ra] = tf32r(v1.z); As[8 + fa * 4 + 3][ra] = tf32r(v1.w);
        }
        // ---- stage B tile into Bs[k][n] ----
        if (TB) {
            const float* bp = B + (size_t)(col0 + ra) * ldb + k0 + fa * 4;
            float4 v0 = *(const float4*)bp;
            float4 v1 = *(const float4*)(bp + 8);
            Bs[fa * 4 + 0][ra] = tf32r(v0.x); Bs[fa * 4 + 1][ra] = tf32r(v0.y);
            Bs[fa * 4 + 2][ra] = tf32r(v0.z); Bs[fa * 4 + 3][ra] = tf32r(v0.w);
            Bs[8 + fa * 4 + 0][ra] = tf32r(v1.x); Bs[8 + fa * 4 + 1][ra] = tf32r(v1.y);
            Bs[8 + fa * 4 + 2][ra] = tf32r(v1.z); Bs[8 + fa * 4 + 3][ra] = tf32r(v1.w);
        } else {
            int kk = t >> 4, cq = t & 15;
            const float* bp = B + (size_t)(k0 + kk) * ldb + col0 + cq * 4;
            float4 v0 = *(const float4*)bp;
            float4 v1 = *(const float4*)(bp + 64);
            float4 w0 = make_float4(tf32r(v0.x), tf32r(v0.y), tf32r(v0.z), tf32r(v0.w));
            float4 w1 = make_float4(tf32r(v1.x), tf32r(v1.y), tf32r(v1.z), tf32r(v1.w));
            *(float4*)&Bs[kk][cq * 4] = w0;
            *(float4*)&Bs[kk][64 + cq * 4] = w1;
        }
        __syncthreads();

#pragma unroll
        for (int kf = 0; kf < 2; kf++) {
            const int kb = kf * 8;
            uint32_t a[2][4], b[8][2];
#pragma unroll
            for (int mt = 0; mt < 2; mt++) {
                int rb = wm * 32 + mt * 16;
                a[mt][0] = __float_as_uint(As[kb + tig][rb + g]);
                a[mt][1] = __float_as_uint(As[kb + tig][rb + g + 8]);
                a[mt][2] = __float_as_uint(As[kb + tig + 4][rb + g]);
                a[mt][3] = __float_as_uint(As[kb + tig + 4][rb + g + 8]);
            }
#pragma unroll
            for (int nt = 0; nt < 8; nt++) {
                int cb = wn * 64 + nt * 8;
                b[nt][0] = __float_as_uint(Bs[kb + tig][cb + g]);
                b[nt][1] = __float_as_uint(Bs[kb + tig + 4][cb + g]);
            }
#pragma unroll
            for (int mt = 0; mt < 2; mt++)
#pragma unroll
                for (int nt = 0; nt < 8; nt++)
                    mma_tf32(acc[mt][nt], a[mt], b[nt]);
        }
        __syncthreads();
    }

    // ---- epilogue ----
#pragma unroll
    for (int mt = 0; mt < 2; mt++) {
        int r0 = row0 + wm * 32 + mt * 16 + g;
#pragma unroll
        for (int nt = 0; nt < 8; nt++) {
            int c = col0 + wn * 64 + nt * 8 + tig * 2;
            float2* p0 = (float2*)(C + (size_t)r0 * ldc + c);
            float2* p1 = (float2*)(C + (size_t)(r0 + 8) * ldc + c);
            if (SUB) {
                float2 v0 = *p0, v1 = *p1;
                v0.x -= acc[mt][nt][0]; v0.y -= acc[mt][nt][1];
                v1.x -= acc[mt][nt][2]; v1.y -= acc[mt][nt][3];
                *p0 = v0; *p1 = v1;
            } else {
                *p0 = make_float2(acc[mt][nt][0], acc[mt][nt][1]);
                *p1 = make_float2(acc[mt][nt][2], acc[mt][nt][3]);
            }
        }
    }
}

__global__ void k_copy_panel(float* __restrict__ dst, const float* __restrict__ src, int rows) {
    int idx = blockIdx.x * 256 + threadIdx.x;
    if (idx >= rows * 32) return;
    int r = idx >> 5, q = idx & 31;
    *(float4*)(dst + (size_t)r * NTR + q * 4) = *(const float4*)(src + (size_t)r * BS + q * 4);
}

// ------------------------------------------------------------- trsv (blocked)
__global__ void k_trsv_diag_fwd(int kb) {
    __shared__ float sb[BS];
    int t = threadIdx.x;
    sb[t] = g_b[kb * BS + t];
    __syncthreads();
    const float* Mi = g_invD + kb * BS * BS + t * BS;
    float s = 0.f;
#pragma unroll 4
    for (int k = 0; k < BS; k++) s += Mi[k] * sb[k];
    g_y[kb * BS + t] = s;
}

__global__ void k_trsv_upd_fwd(int kb) {
    __shared__ float sy[BS];
    int t = threadIdx.x;
    if (t < BS) sy[t] = g_y[kb * BS + t];
    __syncthreads();
    int i = (kb + 1) * BS + blockIdx.x * 256 + t;
    if (i >= NTR) return;
    const float* row = g_L + (size_t)i * NTR + kb * BS;
    float s = 0.f;
#pragma unroll
    for (int q = 0; q < 32; q++) {
        float4 v = *(const float4*)(row + q * 4);
        s += v.x * sy[q * 4] + v.y * sy[q * 4 + 1] + v.z * sy[q * 4 + 2] + v.w * sy[q * 4 + 3];
    }
    g_b[i] -= s;
}

__global__ void k_trsv_diag_bwd(int kb) {
    __shared__ float sb[BS];
    int t = threadIdx.x;
    sb[t] = g_b[kb * BS + t];
    __syncthreads();
    const float* Mi = g_invD + kb * BS * BS;
    float s = 0.f;
#pragma unroll 4
    for (int j = 0; j < BS; j++) s += Mi[j * BS + t] * sb[j];
    g_alpha[kb * BS + t] = s;
}

__global__ void k_trsv_upd_bwd(int kb) {
    __shared__ float sx[BS];
    int t = threadIdx.x;
    if (t < BS) sx[t] = g_alpha[kb * BS + t];
    __syncthreads();
    int i = blockIdx.x * 256 + t;
    if (i >= kb * BS) return;
    float s = 0.f;
#pragma unroll 4
    for (int j = 0; j < BS; j++) s += g_L[(size_t)(kb * BS + j) * NTR + i] * sx[j];
    g_b[i] -= s;
}

__global__ void k_veccopy(float* dst, const float* src, int n) {
    int i = blockIdx.x * 256 + threadIdx.x;
    if (i < n) dst[i] = src[i];
}

// ----------------------------------------------------------- reductions
__global__ void k_part_mean() {
    __shared__ float sa[512];
    int t = threadIdx.x;                 // 128
    int n0 = blockIdx.y * 512;
    for (int q = t; q < 512; q += 128) sa[q] = g_alpha[n0 + q];
    __syncthreads();
    int m = blockIdx.x * 128 + t;
    float s = 0.f;
    for (int q = 0; q < 512; q++) s += g_Ks[(size_t)(n0 + q) * NTE + m] * sa[q];
    g_partM[blockIdx.y * NTE + m] = s;
}

__global__ void k_part_var() {
    int t = threadIdx.x;
    int n0 = blockIdx.y * 512;
    int m = blockIdx.x * 128 + t;
    float s = 0.f;
    for (int q = 0; q < 512; q++) { float v = g_V[(size_t)(n0 + q) * NTE + m]; s += v * v; }
    g_partV[blockIdx.y * NTE + m] = s;
}

__global__ void k_finalize(float* out) {
    int m = blockIdx.x * 256 + threadIdx.x;
    if (m >= NTE) return;
    float sm = 0.f, sv = 0.f;
#pragma unroll
    for (int p = 0; p < 8; p++) { sm += g_partM[p * NTE + m]; sv += g_partV[p * NTE + m]; }
    out[m] = sm;
    out[NTE + m] = g_params[0] + g_params[1] - sv;
}

// ----------------------------------------------------------------- launch
extern "C" void kernel_launch(void* const* d_in, const int* in_sizes, int n_in,
                              void* d_out, int out_size)
{
    const float* train_x = (const float*)d_in[0];
    const float* train_y = (const float*)d_in[1];
    const float* test_x  = (const float*)d_in[2];
    const float* lsf2    = (const float*)d_in[3];
    const float* ll2     = (const float*)d_in[4];
    const float* lsn2    = (const float*)d_in[5];
    float* out = (float*)d_out;

    float *pL, *pKs, *pV, *pInvD, *pPanel, *pXs, *pTs, *pSqx, *pSqt, *pB, *pY;
    cudaGetSymbolAddress((void**)&pL,    g_L);
    cudaGetSymbolAddress((void**)&pKs,   g_Ks);
    cudaGetSymbolAddress((void**)&pV,    g_V);
    cudaGetSymbolAddress((void**)&pInvD, g_invD);
    cudaGetSymbolAddress((void**)&pPanel,g_panel);
    cudaGetSymbolAddress((void**)&pXs,   g_xs);
    cudaGetSymbolAddress((void**)&pTs,   g_ts);
    cudaGetSymbolAddress((void**)&pSqx,  g_sqx);
    cudaGetSymbolAddress((void**)&pSqt,  g_sqt);
    cudaGetSymbolAddress((void**)&pB,    g_b);
    cudaGetSymbolAddress((void**)&pY,    g_y);

    const size_t smem_pi = 2 * BS * (BS + 1) * sizeof(float);  // ~129 KB
    cudaFuncSetAttribute(k_potrf_invert, cudaFuncAttributeMaxDynamicSharedMemorySize,
                         (int)smem_pi);

    k_prep<<<1, 32>>>(lsf2, ll2, lsn2);
    k_scale<<<(NTR + 255) / 256, 256>>>(train_x, pXs, pSqx, NTR);
    k_scale<<<(NTE + 255) / 256, 256>>>(test_x,  pTs, pSqt, NTE);
    k_build_knn<<<dim3(NTR / 32, NTR / 32), 256>>>();
    k_build_ks <<<dim3(NTE / 32, NTR / 32), 256>>>();

    // ---- blocked Cholesky (right-looking), with diag-block inverses ----
    for (int kb = 0; kb < NB; kb++) {
        k_potrf_invert<<<1, 1024, smem_pi>>>(kb);
        int R = NTR - (kb + 1) * BS;
        if (R > 0) {
            const float* A21 = pL + (size_t)(kb + 1) * BS * NTR + kb * BS;
            // panel: L21 = A21 * invL11^T  (NT)
            k_gemm128<1, 0, 0><<<dim3(1, R / BS), 256>>>(
                A21, NTR, pInvD + kb * BS * BS, BS, pPanel, BS);
            k_copy_panel<<<(R * 32 + 255) / 256, 256>>>(
                pL + (size_t)(kb + 1) * BS * NTR + kb * BS, pPanel, R);
            // syrk: A22 -= L21 * L21^T (lower tiles only)
            float* C22 = pL + (size_t)(kb + 1) * BS * NTR + (kb + 1) * BS;
            k_gemm128<1, 1, 1><<<dim3(R / BS, R / BS), 256>>>(
                pPanel, BS, pPanel, BS, C22, NTR);
        }
    }

    // ---- forward trsv: y = L^{-1} train_outputs ----
    k_veccopy<<<(NTR + 255) / 256, 256>>>(pB, train_y, NTR);
    for (int kb = 0; kb < NB; kb++) {
        k_trsv_diag_fwd<<<1, BS>>>(kb);
        int R = NTR - (kb + 1) * BS;
        if (R > 0) k_trsv_upd_fwd<<<(R + 255) / 256, 256>>>(kb);
    }
    // ---- backward trsv: alpha = L^{-T} y ----
    k_veccopy<<<(NTR + 255) / 256, 256>>>(pB, pY, NTR);
    for (int kb = NB - 1; kb >= 0; kb--) {
        k_trsv_diag_bwd<<<1, BS>>>(kb);
        if (kb > 0) k_trsv_upd_bwd<<<(kb * BS + 255) / 256, 256>>>(kb);
    }

    // ---- pred_mean partials (uses intact Kstar, before V solve) ----
    k_part_mean<<<dim3(NTE / 128, 8), 128>>>();

    // ---- V = L^{-1} Kstar (blocked trsm via invDiag; destroys Ks) ----
    for (int kb = 0; kb < NB; kb++) {
        k_gemm128<0, 0, 0><<<dim3(NTE / 128, 1), 256>>>(
            pInvD + kb * BS * BS, BS,
            pKs + (size_t)kb * BS * NTE, NTE,
            pV  + (size_t)kb * BS * NTE, NTE);
        int R = NTR - (kb + 1) * BS;
        if (R > 0) {
            k_gemm128<0, 1, 0><<<dim3(NTE / 128, R / BS), 256>>>(
                pL + (size_t)(kb + 1) * BS * NTR + kb * BS, NTR,
                pV + (size_t)kb * BS * NTE, NTE,
                pKs + (size_t)(kb + 1) * BS * NTE, NTE);
        }
    }

    k_part_var<<<dim3(NTE / 128, 8), 128>>>();
    k_finalize<<<(NTE + 255) / 256, 256>>>(out);
}